// round 13
// baseline (speedup 1.0000x reference)
#include <cuda_runtime.h>

#define BB 64
#define SZ 2048
#define LL 16
#define AA 64
#define HH 256
#define RR 65536
#define XW (SZ + LL)

#define MW1_PITCH 196   // 192 + 4 pad; stride%8==4 -> conflict-free LDS.128 phases
#define MW1_SMEM_BYTES (256 * MW1_PITCH * 4)
#define NSTEP_BLOCKS 512

// ---------------- scratch (static device globals; no allocs) ----------------
__device__ __align__(16) float    g_P1[SZ * HH];
__device__ __align__(16) float    g_P2[SZ * HH];
__device__ __align__(16) unsigned g_relB[RR * 32];        // relation rows, bf16x2 pairs, CSR order
__device__ __align__(16) unsigned g_metaB[LL * BB * 32];  // meta bf16x2 pairs [(t*64+b)*32 + kp]
__device__ __align__(16) float    g_stateAll[LL + 1][SZ * BB]; // [t][o][b]
__device__ int g_perm[RR];
__device__ int g_subjS[RR];
__device__ int g_objS[RR];
__device__ int g_counts[SZ];
__device__ int g_rowptr[SZ + 1];
__device__ int g_offs[SZ];
__device__ unsigned g_barCount;
__device__ volatile unsigned g_barGen;

// ---------------- mma helpers ----------------
__device__ __forceinline__ unsigned f2t(float f) {
    unsigned u;
    asm("cvt.rna.tf32.f32 %0, %1;" : "=r"(u) : "f"(f));
    return u;
}
__device__ __forceinline__ unsigned pk(float lo, float hi) {  // bf16x2 {hi,lo}
    unsigned r;
    asm("cvt.rn.bf16x2.f32 %0, %1, %2;" : "=r"(r) : "f"(hi), "f"(lo));
    return r;
}
__device__ __forceinline__ void mma8(float4& d, unsigned a0, unsigned a1, unsigned a2,
                                     unsigned a3, unsigned b0, unsigned b1) {
    asm volatile(
        "mma.sync.aligned.m16n8k8.row.col.f32.tf32.tf32.f32 "
        "{%0,%1,%2,%3},{%4,%5,%6,%7},{%8,%9},{%0,%1,%2,%3};"
        : "+f"(d.x), "+f"(d.y), "+f"(d.z), "+f"(d.w)
        : "r"(a0), "r"(a1), "r"(a2), "r"(a3), "r"(b0), "r"(b1));
}
__device__ __forceinline__ void mma16(float4& d, unsigned a0, unsigned a1, unsigned a2,
                                      unsigned a3, unsigned b0, unsigned b1) {
    asm volatile(
        "mma.sync.aligned.m16n8k16.row.col.f32.bf16.bf16.f32 "
        "{%0,%1,%2,%3},{%4,%5,%6,%7},{%8,%9},{%0,%1,%2,%3};"
        : "+f"(d.x), "+f"(d.y), "+f"(d.z), "+f"(d.w)
        : "r"(a0), "r"(a1), "r"(a2), "r"(a3), "r"(b0), "r"(b1));
}

__device__ __forceinline__ float sigf(float v) {
    return __fdividef(1.f, 1.f + __expf(-v));
}

// ---------------- CSR build (deterministic) ----------------
__global__ void k_zero() {
    int i = blockIdx.x * blockDim.x + threadIdx.x;
    if (i < SZ) g_counts[i] = 0;
}

__global__ void k_hist(const int* __restrict__ robj) {
    int e = blockIdx.x * blockDim.x + threadIdx.x;
    if (e < RR) atomicAdd(&g_counts[robj[e]], 1);
}

__global__ void k_scan() {  // 1 block, 1024 threads: scan of 2048
    __shared__ int sA[SZ], sB[SZ];
    int tid = threadIdx.x;
    for (int i = tid; i < SZ; i += 1024) sA[i] = g_counts[i];
    __syncthreads();
    int* src = sA; int* dst = sB;
    for (int off = 1; off < SZ; off <<= 1) {
        for (int i = tid; i < SZ; i += 1024)
            dst[i] = src[i] + (i >= off ? src[i - off] : 0);
        __syncthreads();
        int* t = src; src = dst; dst = t;
    }
    for (int i = tid; i < SZ; i += 1024) {
        g_rowptr[i + 1] = src[i];
        g_offs[i] = (i == 0) ? 0 : src[i - 1];
    }
    if (tid == 0) g_rowptr[0] = 0;
}

__global__ void k_scatter(const int* __restrict__ robj) {
    int e = blockIdx.x * blockDim.x + threadIdx.x;
    if (e < RR) {
        int pos = atomicAdd(&g_offs[robj[e]], 1);
        g_perm[pos] = e;
    }
}

// sort each bucket's edge ids ascending (determinism), emit subj/obj in sorted order
__global__ void k_bsort(const int* __restrict__ rsub) {
    __shared__ int buf[8][208];
    int wid = threadIdx.x >> 5, lane = threadIdx.x & 31;
    int o = blockIdx.x * 8 + wid;
    int s = g_rowptr[o], e = g_rowptr[o + 1], n = e - s;
    if (n > 0 && n <= 208) {
        for (int i = lane; i < n; i += 32) buf[wid][i] = g_perm[s + i];
        __syncwarp();
        for (int r = 0; r < n; r++) {           // odd-even transposition
            int par = r & 1;
            for (int i = par + 2 * lane; i + 1 < n; i += 64) {
                int a = buf[wid][i], b = buf[wid][i + 1];
                if (a > b) { buf[wid][i] = b; buf[wid][i + 1] = a; }
            }
            __syncwarp();
        }
        for (int i = lane; i < n; i += 32) {
            int p = buf[wid][i];
            g_perm[s + i] = p;
            g_subjS[s + i] = rsub[p];
            g_objS[s + i] = o;
        }
    } else {
        for (int i = lane; i < n; i += 32) {
            int p = g_perm[s + i];
            g_subjS[s + i] = rsub[p];
            g_objS[s + i] = o;
        }
    }
}

// ---------------- P1/P2 = state_emb @ W1 halves ----------------
__global__ void k_p12(const float* __restrict__ emb, const float* __restrict__ w1) {
    __shared__ float es[8][64];
    int tid = threadIdx.x;
    int r0 = blockIdx.x * 8;
    for (int i = tid; i < 512; i += 256) es[i >> 6][i & 63] = emb[r0 * 64 + i];
    __syncthreads();
    float a1[8], a2[8];
#pragma unroll
    for (int r = 0; r < 8; r++) { a1[r] = 0.f; a2[r] = 0.f; }
    for (int k = 0; k < 64; k++) {
        float wa = w1[k * HH + tid];
        float wb = w1[(64 + k) * HH + tid];
#pragma unroll
        for (int r = 0; r < 8; r++) {
            a1[r] += es[r][k] * wa;
            a2[r] += es[r][k] * wb;
        }
    }
#pragma unroll
    for (int r = 0; r < 8; r++) {
        g_P1[(r0 + r) * HH + tid] = a1[r];
        g_P2[(r0 + r) * HH + tid] = a2[r];
    }
}

// ---------------- meta recurrence: one batch per block, mw1 resident in smem ------
// Runs on a forked stream, overlapped with the CSR/P12/rel2 chain.
__global__ void __launch_bounds__(256) k_meta(
        const int* __restrict__ x, const float* __restrict__ aemb,
        const float* __restrict__ pemb, const float* __restrict__ qw,
        const float* __restrict__ qb, const float* __restrict__ mw1,
        const float* __restrict__ mb1, const float* __restrict__ mw2,
        const float* __restrict__ mb2, const float* __restrict__ minit) {
    extern __shared__ __align__(16) float sW[];   // [256][MW1_PITCH]
    __shared__ __align__(16) float sent[16][132];
    __shared__ __align__(16) float meta[64];
    __shared__ __align__(16) float query[128];
    __shared__ float attn[16];
    __shared__ __align__(16) float z[192];
    __shared__ __align__(16) float hid[256];
    int t = threadIdx.x;
    int b = blockIdx.x;

    for (int k = 0; k < 192; k++) sW[t * MW1_PITCH + k] = mw1[k * HH + t];

    for (int i = t; i < 16 * 128; i += 256) {
        int l = i >> 7, d = i & 127;
        int a = x[b * XW + SZ + l];
        sent[l][d] = (d < 64) ? aemb[a * 64 + d] : pemb[l * 64 + (d - 64)];
    }
    if (t < 64) meta[t] = minit[t];
    __syncthreads();

    for (int st = 0; st < 16; st++) {
        {
            int j = t >> 1, s = t & 1;
            float q = 0.f;
#pragma unroll
            for (int k = s * 32; k < s * 32 + 32; k++) q += meta[k] * qw[k * 128 + j];
            q += __shfl_xor_sync(0xffffffffu, q, 1);
            if (s == 0) query[j] = q + qb[j];
        }
        __syncthreads();
        {
            int l = t >> 4, s = t & 15;
            float sc = 0.f;
#pragma unroll
            for (int i = 0; i < 8; i++) {
                int d = s + 16 * i;
                sc += query[d] * sent[l][d];
            }
            sc += __shfl_xor_sync(0xffffffffu, sc, 1);
            sc += __shfl_xor_sync(0xffffffffu, sc, 2);
            sc += __shfl_xor_sync(0xffffffffu, sc, 4);
            sc += __shfl_xor_sync(0xffffffffu, sc, 8);
            if (s == 0) attn[l] = sc;
        }
        __syncthreads();
        if (t < 16) {
            float v = attn[t];
            float m = v;
#pragma unroll
            for (int o = 8; o; o >>= 1) m = fmaxf(m, __shfl_xor_sync(0xffffu, m, o));
            float e = __expf(v - m);
            float ssum = e;
#pragma unroll
            for (int o = 8; o; o >>= 1) ssum += __shfl_xor_sync(0xffffu, ssum, o);
            attn[t] = e / ssum;
        }
        __syncthreads();
        {
            int j = t >> 1, s = t & 1;
            float at = 0.f;
#pragma unroll
            for (int l = s * 8; l < s * 8 + 8; l++) at += attn[l] * sent[l][j];
            at += __shfl_xor_sync(0xffffffffu, at, 1);
            if (s == 0) {
                z[64 + j] = at;
                if (j < 64) z[j] = meta[j];
            }
        }
        __syncthreads();
        {
            const float4* wrow = (const float4*)&sW[t * MW1_PITCH];
            const float4* z4 = (const float4*)z;
            float a0 = 0.f, a1 = 0.f, a2 = 0.f, a3 = 0.f;
#pragma unroll
            for (int i = 0; i < 48; i += 4) {
                float4 w0 = wrow[i],     zv0 = z4[i];
                float4 w1v = wrow[i + 1], zv1 = z4[i + 1];
                float4 w2v = wrow[i + 2], zv2 = z4[i + 2];
                float4 w3v = wrow[i + 3], zv3 = z4[i + 3];
                a0 += w0.x * zv0.x + w0.y * zv0.y + w0.z * zv0.z + w0.w * zv0.w;
                a1 += w1v.x * zv1.x + w1v.y * zv1.y + w1v.z * zv1.z + w1v.w * zv1.w;
                a2 += w2v.x * zv2.x + w2v.y * zv2.y + w2v.z * zv2.z + w2v.w * zv2.w;
                a3 += w3v.x * zv3.x + w3v.y * zv3.y + w3v.z * zv3.z + w3v.w * zv3.w;
            }
            hid[t] = fmaxf((a0 + a1) + (a2 + a3) + mb1[t], 0.f);
        }
        __syncthreads();
        {
            int j = t >> 2, s = t & 3;
            float a0 = 0.f, a1 = 0.f;
#pragma unroll
            for (int i = 0; i < 64; i += 2) {
                a0 += hid[4 * i + s]       * mw2[(4 * i + s) * 64 + j];
                a1 += hid[4 * (i + 1) + s] * mw2[(4 * (i + 1) + s) * 64 + j];
            }
            float m = a0 + a1;
            m += __shfl_xor_sync(0xffffffffu, m, 1);
            m += __shfl_xor_sync(0xffffffffu, m, 2);
            if (s == 0) meta[j] = m + mb2[j];
        }
        __syncthreads();
        if (t < 32) g_metaB[(st * 64 + b) * 32 + t] = pk(meta[2 * t], meta[2 * t + 1]);
    }
}

// ---------------- relation rows via tf32 mma (CVT hoisted); output bf16 pairs ------
// block: 64 edges, N=64, K=256 in 4 chunks of 64. 256 threads = 8 warps (4m x 2n).
__global__ void k_rel2(const float* __restrict__ b1v, const float* __restrict__ w2,
                       const float* __restrict__ b2v) {
    __shared__ unsigned hs[64][68];   // tf32 bits
    __shared__ unsigned ws[64][68];   // tf32 bits
    __shared__ int ssub[64], sobj[64];
    int tid = threadIdx.x;
    int e0 = blockIdx.x * 64;
    if (tid < 64) { ssub[tid] = g_subjS[e0 + tid]; sobj[tid] = g_objS[e0 + tid]; }
    __syncthreads();
    int warp = tid >> 5, lane = tid & 31;
    int wm = warp & 3, wn = warp >> 2;
    int g = lane >> 2, tg = lane & 3;
    int r0 = wm * 16, n0 = wn * 32;
    float4 acc[4] = {};
    for (int kc = 0; kc < 4; kc++) {
        for (int i = tid; i < 64 * 16; i += 256) {
            int r = i >> 4, c = (i & 15) * 4;
            float4 p1 = *(const float4*)&g_P1[ssub[r] * HH + kc * 64 + c];
            float4 p2 = *(const float4*)&g_P2[sobj[r] * HH + kc * 64 + c];
            float4 bb = *(const float4*)&b1v[kc * 64 + c];
            uint4 h;
            h.x = f2t(fmaxf(p1.x + p2.x + bb.x, 0.f));
            h.y = f2t(fmaxf(p1.y + p2.y + bb.y, 0.f));
            h.z = f2t(fmaxf(p1.z + p2.z + bb.z, 0.f));
            h.w = f2t(fmaxf(p1.w + p2.w + bb.w, 0.f));
            *(uint4*)&hs[r][c] = h;
            float4 w = *(const float4*)&w2[(kc * 64 + r) * 64 + c];
            uint4 wv = {f2t(w.x), f2t(w.y), f2t(w.z), f2t(w.w)};
            *(uint4*)&ws[r][c] = wv;
        }
        __syncthreads();
#pragma unroll
        for (int ks = 0; ks < 8; ks++) {
            int kk = ks * 8;
            unsigned a0 = hs[r0 + g][kk + tg];
            unsigned a1 = hs[r0 + g + 8][kk + tg];
            unsigned a2 = hs[r0 + g][kk + tg + 4];
            unsigned a3 = hs[r0 + g + 8][kk + tg + 4];
#pragma unroll
            for (int nf = 0; nf < 4; nf++) {
                int n = n0 + nf * 8 + g;
                mma8(acc[nf], a0, a1, a2, a3, ws[kk + tg][n], ws[kk + tg + 4][n]);
            }
        }
        __syncthreads();
    }
#pragma unroll
    for (int nf = 0; nf < 4; nf++) {
        int col = n0 + nf * 8 + 2 * tg;
        float bx = b2v[col], by = b2v[col + 1];
        int row = e0 + r0 + g;
        int pi = (n0 + nf * 8) / 2 + tg;   // pair index = col/2
        g_relB[row * 32 + pi] = pk(acc[nf].x + bx, acc[nf].y + by);
        g_relB[(row + 8) * 32 + pi] = pk(acc[nf].z + bx, acc[nf].w + by);
    }
}

// ---------------- init: state[0] from x, zero state[1] ----------------
__global__ void k_init(const int* __restrict__ x) {
    int i = blockIdx.x * blockDim.x + threadIdx.x;  // 131072
    int b = i >> 11, o = i & 2047;
    g_stateAll[0][o * 64 + b] = (float)x[b * XW + o];
    g_stateAll[1][i] = 0.f;
}

// ---------------- persistent step kernel: all 16 steps, one launch ----------------
// 512 blocks x 256 threads, 4 blocks/SM guaranteed (smem 45KB, regs capped at 64).
// rel tile + ids staged once; per step: 8KB meta reload + MMA + gather + reduce.
// Software grid barrier (sense-reversing generation counter) between steps.
__global__ void __launch_bounds__(256, 4) k_stepAll() {
    __shared__ __align__(16) float prod[64 * 68];
    __shared__ __align__(16) unsigned relS[2][64 * 36];
    __shared__ __align__(16) unsigned metaS[64 * 36];
    __shared__ int ssubj[2][64];
    __shared__ int sobj[2][64];
    int tid = threadIdx.x;
    int e0 = blockIdx.x * 128;

    // one-time staging: rel tiles (both halves) + ids
    for (int i = tid; i < 1024; i += 256) {
        int r = i >> 3, c4 = (i & 7) * 4;          // r in 0..127
        int h = r >> 6, rr = r & 63;
        *(uint4*)&relS[h][rr * 36 + c4] = *(const uint4*)&g_relB[(e0 + r) * 32 + c4];
    }
    if (tid < 128) {
        int h = tid >> 6, r = tid & 63;
        ssubj[h][r] = g_subjS[e0 + h * 64 + r];
        sobj[h][r] = g_objS[e0 + h * 64 + r];
    }

    int warp = tid >> 5, lane = tid & 31;
    int wm = warp & 3, wn = warp >> 2;
    int g = lane >> 2, tg = lane & 3;
    int r0 = wm * 16, n0 = wn * 32;
    int rA = r0 + g, rB = rA + 8;
    int q = tid >> 6, col = tid & 63;

    for (int t = 0; t < LL; t++) {
        const float* __restrict__ stIn = g_stateAll[t];
        float* __restrict__ stOut = g_stateAll[t + 1];
        const unsigned* mt = &g_metaB[t * 2048];
        for (int i = tid; i < 512; i += 256) {
            int r = i >> 3, c4 = (i & 7) * 4;
            *(uint4*)&metaS[r * 36 + c4] = *(const uint4*)&mt[r * 32 + c4];
        }
        if (t + 2 <= LL) g_stateAll[t + 2][blockIdx.x * 256 + tid] = 0.f;
        __syncthreads();

#pragma unroll
        for (int h = 0; h < 2; h++) {
            float4 accf[4] = {};
#pragma unroll
            for (int ks = 0; ks < 4; ks++) {
                int kp = ks * 8;
                unsigned a0 = relS[h][rA * 36 + kp + tg];
                unsigned a1 = relS[h][rB * 36 + kp + tg];
                unsigned a2 = relS[h][rA * 36 + kp + tg + 4];
                unsigned a3 = relS[h][rB * 36 + kp + tg + 4];
#pragma unroll
                for (int nf = 0; nf < 4; nf++) {
                    int n = n0 + nf * 8 + g;
                    mma16(accf[nf], a0, a1, a2, a3,
                          metaS[n * 36 + kp + tg], metaS[n * 36 + kp + tg + 4]);
                }
            }
            // epilogue: prod[e][b] = state[subj[e]][b] * sigmoid(D[e][b])
            int sjA = ssubj[h][rA], sjB = ssubj[h][rB];
#pragma unroll
            for (int nf = 0; nf < 4; nf++) {
                int c = n0 + nf * 8 + 2 * tg;
                float2 svA = __ldcg((const float2*)&stIn[sjA * 64 + c]);
                float2 svB = __ldcg((const float2*)&stIn[sjB * 64 + c]);
                float2 pA = {svA.x * sigf(accf[nf].x), svA.y * sigf(accf[nf].y)};
                float2 pB = {svB.x * sigf(accf[nf].z), svB.y * sigf(accf[nf].w)};
                *(float2*)&prod[rA * 68 + c] = pA;
                *(float2*)&prod[rB * 68 + c] = pB;
            }
            __syncthreads();
            // run-segmented reduction -> global atomics (buckets may span blocks)
            {
                float s = 0.f;
                int cur = sobj[h][q * 16];
#pragma unroll
                for (int r = q * 16; r < q * 16 + 16; r++) {
                    int o = sobj[h][r];
                    if (o != cur) {
                        atomicAdd(&stOut[cur * 64 + col], s);
                        s = 0.f; cur = o;
                    }
                    s += prod[r * 68 + col];
                }
                atomicAdd(&stOut[cur * 64 + col], s);
            }
            if (h == 0) __syncthreads();  // reduce reads done before prod rewrite
        }

        // grid-wide barrier between steps (not after the last)
        if (t < LL - 1) {
            __syncthreads();
            if (tid == 0) {
                unsigned gen = g_barGen;
                __threadfence();
                if (atomicAdd(&g_barCount, 1u) == (unsigned)(NSTEP_BLOCKS - 1)) {
                    g_barCount = 0;
                    __threadfence();
                    g_barGen = gen + 1;
                } else {
                    while (g_barGen == gen) { }
                    __threadfence();
                }
            }
            __syncthreads();
        }
    }
}

// ---------------- final transpose: out[b][t][o] = stateAll[t+1][o][b] -------------
__global__ void k_out(float* __restrict__ out) {
    __shared__ float tile[64][65];
    int t = blockIdx.x, o0 = blockIdx.y * 64;
    const float* st = g_stateAll[t + 1];
    for (int i = threadIdx.x; i < 64 * 64; i += 256) {
        int r = i >> 6, b = i & 63;
        tile[b][r] = st[(o0 + r) * 64 + b];
    }
    __syncthreads();
    for (int i = threadIdx.x; i < 64 * 64; i += 256) {
        int b = i >> 6, c = i & 63;
        out[(size_t)b * (LL * SZ) + t * SZ + o0 + c] = tile[b][c];
    }
}

extern "C" void kernel_launch(void* const* d_in, const int* in_sizes, int n_in,
                              void* d_out, int out_size) {
    const int*   x     = (const int*)d_in[0];
    const int*   rsub  = (const int*)d_in[1];
    const int*   robj  = (const int*)d_in[2];
    const float* aemb  = (const float*)d_in[3];
    const float* pemb  = (const float*)d_in[4];
    const float* semb  = (const float*)d_in[5];
    const float* w1    = (const float*)d_in[6];
    const float* b1    = (const float*)d_in[7];
    const float* w2    = (const float*)d_in[8];
    const float* b2    = (const float*)d_in[9];
    const float* qw    = (const float*)d_in[10];
    const float* qb    = (const float*)d_in[11];
    const float* mw1   = (const float*)d_in[12];
    const float* mb1   = (const float*)d_in[13];
    const float* mw2   = (const float*)d_in[14];
    const float* mb2   = (const float*)d_in[15];
    const float* minit = (const float*)d_in[16];
    float* out = (float*)d_out;

    // One-time resources: created on the FIRST (uncaptured) correctness call,
    // reused by the capture call. No device-memory allocation involved.
    static cudaStream_t s1 = nullptr;
    static cudaEvent_t evF = nullptr, evJ = nullptr;
    if (s1 == nullptr) {
        cudaStreamCreateWithFlags(&s1, cudaStreamNonBlocking);
        cudaEventCreateWithFlags(&evF, cudaEventDisableTiming);
        cudaEventCreateWithFlags(&evJ, cudaEventDisableTiming);
        cudaFuncSetAttribute(k_meta, cudaFuncAttributeMaxDynamicSharedMemorySize,
                             MW1_SMEM_BYTES);
    }

    // Fork: meta recurrence on s1, CSR/P12/rel2 chain on the main stream.
    k_zero<<<8, 256>>>();
    k_hist<<<256, 256>>>(robj);
    k_scan<<<1, 1024>>>();
    cudaEventRecord(evF, 0);
    cudaStreamWaitEvent(s1, evF, 0);
    k_meta<<<64, 256, MW1_SMEM_BYTES, s1>>>(x, aemb, pemb, qw, qb, mw1, mb1, mw2,
                                            mb2, minit);
    k_scatter<<<256, 256>>>(robj);
    k_bsort<<<256, 256>>>(rsub);
    k_p12<<<256, 256>>>(semb, w1);
    k_rel2<<<1024, 256>>>(b1, w2, b2);
    k_init<<<512, 256>>>(x);
    cudaEventRecord(evJ, s1);
    cudaStreamWaitEvent(0, evJ, 0);

    k_stepAll<<<NSTEP_BLOCKS, 256>>>();
    k_out<<<dim3(16, 32), 256>>>(out);
}

// round 14
// speedup vs baseline: 1.0161x; 1.0161x over previous
#include <cuda_runtime.h>

#define BB 64
#define SZ 2048
#define LL 16
#define AA 64
#define HH 256
#define RR 65536
#define XW (SZ + LL)

#define MW1_PITCH 196   // 192 + 4 pad; stride%8==4 -> conflict-free LDS.128 phases
#define MW1_SMEM_BYTES (256 * MW1_PITCH * 4)

// ---------------- scratch (static device globals; no allocs) ----------------
__device__ __align__(16) float    g_P1[SZ * HH];
__device__ __align__(16) float    g_P2[SZ * HH];
__device__ __align__(16) unsigned g_relB[RR * 32];        // relation rows, bf16x2 pairs, CSR order
__device__ __align__(16) unsigned g_metaB[LL * BB * 32];  // meta bf16x2 pairs [(t*64+b)*32 + kp]
__device__ __align__(16) float    g_stateAll[LL + 1][SZ * BB]; // [t][o][b]
__device__ int g_perm[RR];
__device__ int g_subjS[RR];
__device__ int g_objS[RR];
__device__ int g_counts[SZ];      // zero-initialized at load; re-zeroed by k_scatter
__device__ int g_rowptr[SZ + 1];
__device__ int g_offs[SZ];

// ---------------- mma helpers ----------------
__device__ __forceinline__ unsigned f2t(float f) {
    unsigned u;
    asm("cvt.rna.tf32.f32 %0, %1;" : "=r"(u) : "f"(f));
    return u;
}
__device__ __forceinline__ unsigned pk(float lo, float hi) {  // bf16x2 {hi,lo}
    unsigned r;
    asm("cvt.rn.bf16x2.f32 %0, %1, %2;" : "=r"(r) : "f"(hi), "f"(lo));
    return r;
}
__device__ __forceinline__ void mma8(float4& d, unsigned a0, unsigned a1, unsigned a2,
                                     unsigned a3, unsigned b0, unsigned b1) {
    asm volatile(
        "mma.sync.aligned.m16n8k8.row.col.f32.tf32.tf32.f32 "
        "{%0,%1,%2,%3},{%4,%5,%6,%7},{%8,%9},{%0,%1,%2,%3};"
        : "+f"(d.x), "+f"(d.y), "+f"(d.z), "+f"(d.w)
        : "r"(a0), "r"(a1), "r"(a2), "r"(a3), "r"(b0), "r"(b1));
}
__device__ __forceinline__ void mma16(float4& d, unsigned a0, unsigned a1, unsigned a2,
                                      unsigned a3, unsigned b0, unsigned b1) {
    asm volatile(
        "mma.sync.aligned.m16n8k16.row.col.f32.bf16.bf16.f32 "
        "{%0,%1,%2,%3},{%4,%5,%6,%7},{%8,%9},{%0,%1,%2,%3};"
        : "+f"(d.x), "+f"(d.y), "+f"(d.z), "+f"(d.w)
        : "r"(a0), "r"(a1), "r"(a2), "r"(a3), "r"(b0), "r"(b1));
}

__device__ __forceinline__ float sigf(float v) {
    return __fdividef(1.f, 1.f + __expf(-v));
}

// ---------------- CSR build (deterministic) ----------------
__global__ void k_hist(const int* __restrict__ robj) {
    int e = blockIdx.x * blockDim.x + threadIdx.x;
    if (e < RR) atomicAdd(&g_counts[robj[e]], 1);
}

__global__ void k_scan() {  // 1 block, 1024 threads: scan of 2048
    __shared__ int sA[SZ], sB[SZ];
    int tid = threadIdx.x;
    for (int i = tid; i < SZ; i += 1024) sA[i] = g_counts[i];
    __syncthreads();
    int* src = sA; int* dst = sB;
    for (int off = 1; off < SZ; off <<= 1) {
        for (int i = tid; i < SZ; i += 1024)
            dst[i] = src[i] + (i >= off ? src[i - off] : 0);
        __syncthreads();
        int* t = src; src = dst; dst = t;
    }
    for (int i = tid; i < SZ; i += 1024) {
        g_rowptr[i + 1] = src[i];
        g_offs[i] = (i == 0) ? 0 : src[i - 1];
    }
    if (tid == 0) g_rowptr[0] = 0;
}

__global__ void k_scatter(const int* __restrict__ robj) {
    int e = blockIdx.x * blockDim.x + threadIdx.x;
    if (e < RR) {
        int pos = atomicAdd(&g_offs[robj[e]], 1);
        g_perm[pos] = e;
    }
    // counts already consumed by k_scan; zero for the NEXT kernel_launch call
    // (graph replays run this identically; g_counts is zero-init at load).
    if (e < SZ) g_counts[e] = 0;
}

// sort each bucket's edge ids ascending (determinism), emit subj/obj in sorted order
__global__ void k_bsort(const int* __restrict__ rsub) {
    __shared__ int buf[8][208];
    int wid = threadIdx.x >> 5, lane = threadIdx.x & 31;
    int o = blockIdx.x * 8 + wid;
    int s = g_rowptr[o], e = g_rowptr[o + 1], n = e - s;
    if (n > 0 && n <= 208) {
        for (int i = lane; i < n; i += 32) buf[wid][i] = g_perm[s + i];
        __syncwarp();
        for (int r = 0; r < n; r++) {           // odd-even transposition
            int par = r & 1;
            for (int i = par + 2 * lane; i + 1 < n; i += 64) {
                int a = buf[wid][i], b = buf[wid][i + 1];
                if (a > b) { buf[wid][i] = b; buf[wid][i + 1] = a; }
            }
            __syncwarp();
        }
        for (int i = lane; i < n; i += 32) {
            int p = buf[wid][i];
            g_perm[s + i] = p;
            g_subjS[s + i] = rsub[p];
            g_objS[s + i] = o;
        }
    } else {
        for (int i = lane; i < n; i += 32) {
            int p = g_perm[s + i];
            g_subjS[s + i] = rsub[p];
            g_objS[s + i] = o;
        }
    }
}

// ---------------- P1/P2 = state_emb @ W1 halves ----------------
__global__ void k_p12(const float* __restrict__ emb, const float* __restrict__ w1) {
    __shared__ float es[8][64];
    int tid = threadIdx.x;
    int r0 = blockIdx.x * 8;
    for (int i = tid; i < 512; i += 256) es[i >> 6][i & 63] = emb[r0 * 64 + i];
    __syncthreads();
    float a1[8], a2[8];
#pragma unroll
    for (int r = 0; r < 8; r++) { a1[r] = 0.f; a2[r] = 0.f; }
    for (int k = 0; k < 64; k++) {
        float wa = w1[k * HH + tid];
        float wb = w1[(64 + k) * HH + tid];
#pragma unroll
        for (int r = 0; r < 8; r++) {
            a1[r] += es[r][k] * wa;
            a2[r] += es[r][k] * wb;
        }
    }
#pragma unroll
    for (int r = 0; r < 8; r++) {
        g_P1[(r0 + r) * HH + tid] = a1[r];
        g_P2[(r0 + r) * HH + tid] = a2[r];
    }
}

// ---------------- meta recurrence: one batch per block, mw1 resident in smem ------
// Runs on a forked stream, overlapped with the CSR/P12/rel2 chain.
__global__ void __launch_bounds__(256) k_meta(
        const int* __restrict__ x, const float* __restrict__ aemb,
        const float* __restrict__ pemb, const float* __restrict__ qw,
        const float* __restrict__ qb, const float* __restrict__ mw1,
        const float* __restrict__ mb1, const float* __restrict__ mw2,
        const float* __restrict__ mb2, const float* __restrict__ minit) {
    extern __shared__ __align__(16) float sW[];   // [256][MW1_PITCH]
    __shared__ __align__(16) float sent[16][132];
    __shared__ __align__(16) float meta[64];
    __shared__ __align__(16) float query[128];
    __shared__ float attn[16];
    __shared__ __align__(16) float z[192];
    __shared__ __align__(16) float hid[256];
    int t = threadIdx.x;
    int b = blockIdx.x;

    for (int k = 0; k < 192; k++) sW[t * MW1_PITCH + k] = mw1[k * HH + t];

    for (int i = t; i < 16 * 128; i += 256) {
        int l = i >> 7, d = i & 127;
        int a = x[b * XW + SZ + l];
        sent[l][d] = (d < 64) ? aemb[a * 64 + d] : pemb[l * 64 + (d - 64)];
    }
    if (t < 64) meta[t] = minit[t];
    __syncthreads();

    for (int st = 0; st < 16; st++) {
        {
            int j = t >> 1, s = t & 1;
            float q = 0.f;
#pragma unroll
            for (int k = s * 32; k < s * 32 + 32; k++) q += meta[k] * qw[k * 128 + j];
            q += __shfl_xor_sync(0xffffffffu, q, 1);
            if (s == 0) query[j] = q + qb[j];
        }
        __syncthreads();
        {
            int l = t >> 4, s = t & 15;
            float sc = 0.f;
#pragma unroll
            for (int i = 0; i < 8; i++) {
                int d = s + 16 * i;
                sc += query[d] * sent[l][d];
            }
            sc += __shfl_xor_sync(0xffffffffu, sc, 1);
            sc += __shfl_xor_sync(0xffffffffu, sc, 2);
            sc += __shfl_xor_sync(0xffffffffu, sc, 4);
            sc += __shfl_xor_sync(0xffffffffu, sc, 8);
            if (s == 0) attn[l] = sc;
        }
        __syncthreads();
        if (t < 16) {
            float v = attn[t];
            float m = v;
#pragma unroll
            for (int o = 8; o; o >>= 1) m = fmaxf(m, __shfl_xor_sync(0xffffu, m, o));
            float e = __expf(v - m);
            float ssum = e;
#pragma unroll
            for (int o = 8; o; o >>= 1) ssum += __shfl_xor_sync(0xffffu, ssum, o);
            attn[t] = e / ssum;
        }
        __syncthreads();
        {
            int j = t >> 1, s = t & 1;
            float at = 0.f;
#pragma unroll
            for (int l = s * 8; l < s * 8 + 8; l++) at += attn[l] * sent[l][j];
            at += __shfl_xor_sync(0xffffffffu, at, 1);
            if (s == 0) {
                z[64 + j] = at;
                if (j < 64) z[j] = meta[j];
            }
        }
        __syncthreads();
        {
            const float4* wrow = (const float4*)&sW[t * MW1_PITCH];
            const float4* z4 = (const float4*)z;
            float a0 = 0.f, a1 = 0.f, a2 = 0.f, a3 = 0.f;
#pragma unroll
            for (int i = 0; i < 48; i += 4) {
                float4 w0 = wrow[i],     zv0 = z4[i];
                float4 w1v = wrow[i + 1], zv1 = z4[i + 1];
                float4 w2v = wrow[i + 2], zv2 = z4[i + 2];
                float4 w3v = wrow[i + 3], zv3 = z4[i + 3];
                a0 += w0.x * zv0.x + w0.y * zv0.y + w0.z * zv0.z + w0.w * zv0.w;
                a1 += w1v.x * zv1.x + w1v.y * zv1.y + w1v.z * zv1.z + w1v.w * zv1.w;
                a2 += w2v.x * zv2.x + w2v.y * zv2.y + w2v.z * zv2.z + w2v.w * zv2.w;
                a3 += w3v.x * zv3.x + w3v.y * zv3.y + w3v.z * zv3.z + w3v.w * zv3.w;
            }
            hid[t] = fmaxf((a0 + a1) + (a2 + a3) + mb1[t], 0.f);
        }
        __syncthreads();
        {
            int j = t >> 2, s = t & 3;
            float a0 = 0.f, a1 = 0.f;
#pragma unroll
            for (int i = 0; i < 64; i += 2) {
                a0 += hid[4 * i + s]       * mw2[(4 * i + s) * 64 + j];
                a1 += hid[4 * (i + 1) + s] * mw2[(4 * (i + 1) + s) * 64 + j];
            }
            float m = a0 + a1;
            m += __shfl_xor_sync(0xffffffffu, m, 1);
            m += __shfl_xor_sync(0xffffffffu, m, 2);
            if (s == 0) meta[j] = m + mb2[j];
        }
        __syncthreads();
        if (t < 32) g_metaB[(st * 64 + b) * 32 + t] = pk(meta[2 * t], meta[2 * t + 1]);
    }
}

// ---------------- relation rows via tf32 mma (CVT hoisted); output bf16 pairs ------
// block: 64 edges, N=64, K=256 in 4 chunks of 64. 256 threads = 8 warps (4m x 2n).
__global__ void k_rel2(const float* __restrict__ b1v, const float* __restrict__ w2,
                       const float* __restrict__ b2v) {
    __shared__ unsigned hs[64][68];   // tf32 bits
    __shared__ unsigned ws[64][68];   // tf32 bits
    __shared__ int ssub[64], sobj[64];
    int tid = threadIdx.x;
    int e0 = blockIdx.x * 64;
    if (tid < 64) { ssub[tid] = g_subjS[e0 + tid]; sobj[tid] = g_objS[e0 + tid]; }
    __syncthreads();
    int warp = tid >> 5, lane = tid & 31;
    int wm = warp & 3, wn = warp >> 2;
    int g = lane >> 2, tg = lane & 3;
    int r0 = wm * 16, n0 = wn * 32;
    float4 acc[4] = {};
    for (int kc = 0; kc < 4; kc++) {
        for (int i = tid; i < 64 * 16; i += 256) {
            int r = i >> 4, c = (i & 15) * 4;
            float4 p1 = *(const float4*)&g_P1[ssub[r] * HH + kc * 64 + c];
            float4 p2 = *(const float4*)&g_P2[sobj[r] * HH + kc * 64 + c];
            float4 bb = *(const float4*)&b1v[kc * 64 + c];
            uint4 h;
            h.x = f2t(fmaxf(p1.x + p2.x + bb.x, 0.f));
            h.y = f2t(fmaxf(p1.y + p2.y + bb.y, 0.f));
            h.z = f2t(fmaxf(p1.z + p2.z + bb.z, 0.f));
            h.w = f2t(fmaxf(p1.w + p2.w + bb.w, 0.f));
            *(uint4*)&hs[r][c] = h;
            float4 w = *(const float4*)&w2[(kc * 64 + r) * 64 + c];
            uint4 wv = {f2t(w.x), f2t(w.y), f2t(w.z), f2t(w.w)};
            *(uint4*)&ws[r][c] = wv;
        }
        __syncthreads();
#pragma unroll
        for (int ks = 0; ks < 8; ks++) {
            int kk = ks * 8;
            unsigned a0 = hs[r0 + g][kk + tg];
            unsigned a1 = hs[r0 + g + 8][kk + tg];
            unsigned a2 = hs[r0 + g][kk + tg + 4];
            unsigned a3 = hs[r0 + g + 8][kk + tg + 4];
#pragma unroll
            for (int nf = 0; nf < 4; nf++) {
                int n = n0 + nf * 8 + g;
                mma8(acc[nf], a0, a1, a2, a3, ws[kk + tg][n], ws[kk + tg + 4][n]);
            }
        }
        __syncthreads();
    }
#pragma unroll
    for (int nf = 0; nf < 4; nf++) {
        int col = n0 + nf * 8 + 2 * tg;
        float bx = b2v[col], by = b2v[col + 1];
        int row = e0 + r0 + g;
        int pi = (n0 + nf * 8) / 2 + tg;   // pair index = col/2
        g_relB[row * 32 + pi] = pk(acc[nf].x + bx, acc[nf].y + by);
        g_relB[(row + 8) * 32 + pi] = pk(acc[nf].z + bx, acc[nf].w + by);
    }
}

// ---------------- init: state[0] from x, zero state[1] ----------------
__global__ void k_init(const int* __restrict__ x) {
    int i = blockIdx.x * blockDim.x + threadIdx.x;  // 131072
    int b = i >> 11, o = i & 2047;
    g_stateAll[0][o * 64 + b] = (float)x[b * XW + o];
    g_stateAll[1][i] = 0.f;
}

// ---------------- fused step, bf16: 512 blocks x two 64-edge tiles (one wave) ------
// bf16 m16n8k16 dots + prefetched state gather + sigmoid + run-segmented atomics.
// Also zeros state[t+2] (the NEXT step's accumulation target).
__global__ void __launch_bounds__(256) k_stepG(int t) {
    __shared__ __align__(16) float prod[64 * 68];
    __shared__ __align__(16) unsigned relS[2][64 * 36];
    __shared__ __align__(16) unsigned metaS[64 * 36];
    __shared__ int ssubj[2][64];
    __shared__ int sobj[2][64];
    const float* __restrict__ stIn = g_stateAll[t];
    float* __restrict__ stOut = g_stateAll[t + 1];
    int tid = threadIdx.x;
    int e0 = blockIdx.x * 128;

    const unsigned* mt = &g_metaB[t * 2048];
    for (int i = tid; i < 512; i += 256) {
        int r = i >> 3, c4 = (i & 7) * 4;
        *(uint4*)&metaS[r * 36 + c4] = *(const uint4*)&mt[r * 32 + c4];
        *(uint4*)&relS[0][r * 36 + c4] = *(const uint4*)&g_relB[(e0 + r) * 32 + c4];
        *(uint4*)&relS[1][r * 36 + c4] = *(const uint4*)&g_relB[(e0 + 64 + r) * 32 + c4];
    }
    if (tid < 128) {
        int h = tid >> 6, r = tid & 63;
        ssubj[h][r] = g_subjS[e0 + h * 64 + r];
        sobj[h][r] = g_objS[e0 + h * 64 + r];
    }
    if (t + 2 <= LL && tid < 64) {
        ((float4*)&g_stateAll[t + 2][blockIdx.x * 256])[tid] =
            make_float4(0.f, 0.f, 0.f, 0.f);
    }
    __syncthreads();

    int warp = tid >> 5, lane = tid & 31;
    int wm = warp & 3, wn = warp >> 2;
    int g = lane >> 2, tg = lane & 3;
    int r0 = wm * 16, n0 = wn * 32;
    int rA = r0 + g, rB = rA + 8;
    int q = tid >> 6, col = tid & 63;

    // prefetch state gathers for tile 0 (hidden behind the MMA stream)
    float2 pre[8];
    {
        int sjA = ssubj[0][rA], sjB = ssubj[0][rB];
#pragma unroll
        for (int nf = 0; nf < 4; nf++) {
            int c = n0 + nf * 8 + 2 * tg;
            pre[nf]     = __ldcg((const float2*)&stIn[sjA * 64 + c]);
            pre[4 + nf] = __ldcg((const float2*)&stIn[sjB * 64 + c]);
        }
    }

#pragma unroll
    for (int h = 0; h < 2; h++) {
        float4 accf[4] = {};
#pragma unroll
        for (int ks = 0; ks < 4; ks++) {
            int kp = ks * 8;
            unsigned a0 = relS[h][rA * 36 + kp + tg];
            unsigned a1 = relS[h][rB * 36 + kp + tg];
            unsigned a2 = relS[h][rA * 36 + kp + tg + 4];
            unsigned a3 = relS[h][rB * 36 + kp + tg + 4];
#pragma unroll
            for (int nf = 0; nf < 4; nf++) {
                int n = n0 + nf * 8 + g;
                mma16(accf[nf], a0, a1, a2, a3,
                      metaS[n * 36 + kp + tg], metaS[n * 36 + kp + tg + 4]);
            }
        }

        // epilogue: prod[e][b] = state[subj[e]][b] * sigmoid(D[e][b])
#pragma unroll
        for (int nf = 0; nf < 4; nf++) {
            int c = n0 + nf * 8 + 2 * tg;
            float2 svA = pre[nf];
            float2 svB = pre[4 + nf];
            float2 pA = {svA.x * sigf(accf[nf].x), svA.y * sigf(accf[nf].y)};
            float2 pB = {svB.x * sigf(accf[nf].z), svB.y * sigf(accf[nf].w)};
            *(float2*)&prod[rA * 68 + c] = pA;
            *(float2*)&prod[rB * 68 + c] = pB;
        }
        if (h == 0) {   // prefetch tile 1's gathers before the barrier
            int sjA = ssubj[1][rA], sjB = ssubj[1][rB];
#pragma unroll
            for (int nf = 0; nf < 4; nf++) {
                int c = n0 + nf * 8 + 2 * tg;
                pre[nf]     = __ldcg((const float2*)&stIn[sjA * 64 + c]);
                pre[4 + nf] = __ldcg((const float2*)&stIn[sjB * 64 + c]);
            }
        }
        __syncthreads();

        // run-segmented reduction: thread (q,col) sums rows [16q,16q+16) by bucket,
        // emitting one global atomicAdd per run (buckets may span blocks).
        {
            float s = 0.f;
            int cur = sobj[h][q * 16];
#pragma unroll
            for (int r = q * 16; r < q * 16 + 16; r++) {
                int o = sobj[h][r];
                if (o != cur) {
                    atomicAdd(&stOut[cur * 64 + col], s);
                    s = 0.f; cur = o;
                }
                s += prod[r * 68 + col];
            }
            atomicAdd(&stOut[cur * 64 + col], s);
        }
        if (h == 0) __syncthreads();  // all reduce reads done before prod rewrite
    }
}

// ---------------- final transpose: out[b][t][o] = stateAll[t+1][o][b] -------------
__global__ void k_out(float* __restrict__ out) {
    __shared__ float tile[64][65];
    int t = blockIdx.x, o0 = blockIdx.y * 64;
    const float* st = g_stateAll[t + 1];
    for (int i = threadIdx.x; i < 64 * 64; i += 256) {
        int r = i >> 6, b = i & 63;
        tile[b][r] = st[(o0 + r) * 64 + b];
    }
    __syncthreads();
    for (int i = threadIdx.x; i < 64 * 64; i += 256) {
        int b = i >> 6, c = i & 63;
        out[(size_t)b * (LL * SZ) + t * SZ + o0 + c] = tile[b][c];
    }
}

extern "C" void kernel_launch(void* const* d_in, const int* in_sizes, int n_in,
                              void* d_out, int out_size) {
    const int*   x     = (const int*)d_in[0];
    const int*   rsub  = (const int*)d_in[1];
    const int*   robj  = (const int*)d_in[2];
    const float* aemb  = (const float*)d_in[3];
    const float* pemb  = (const float*)d_in[4];
    const float* semb  = (const float*)d_in[5];
    const float* w1    = (const float*)d_in[6];
    const float* b1    = (const float*)d_in[7];
    const float* w2    = (const float*)d_in[8];
    const float* b2    = (const float*)d_in[9];
    const float* qw    = (const float*)d_in[10];
    const float* qb    = (const float*)d_in[11];
    const float* mw1   = (const float*)d_in[12];
    const float* mb1   = (const float*)d_in[13];
    const float* mw2   = (const float*)d_in[14];
    const float* mb2   = (const float*)d_in[15];
    const float* minit = (const float*)d_in[16];
    float* out = (float*)d_out;

    // One-time resources: created on the FIRST (uncaptured) correctness call,
    // reused by the capture call. No device-memory allocation involved.
    static cudaStream_t s1 = nullptr;
    static cudaEvent_t evF = nullptr, evJ = nullptr;
    if (s1 == nullptr) {
        cudaStreamCreateWithFlags(&s1, cudaStreamNonBlocking);
        cudaEventCreateWithFlags(&evF, cudaEventDisableTiming);
        cudaEventCreateWithFlags(&evJ, cudaEventDisableTiming);
        cudaFuncSetAttribute(k_meta, cudaFuncAttributeMaxDynamicSharedMemorySize,
                             MW1_SMEM_BYTES);
    }

    // Fork: meta recurrence on s1, CSR/P12/rel2 chain on the main stream.
    // g_counts is zero at this point (static init on first call; re-zeroed by
    // the previous call's k_scatter on later calls).
    k_hist<<<256, 256>>>(robj);
    k_scan<<<1, 1024>>>();
    cudaEventRecord(evF, 0);
    cudaStreamWaitEvent(s1, evF, 0);
    k_meta<<<64, 256, MW1_SMEM_BYTES, s1>>>(x, aemb, pemb, qw, qb, mw1, mb1, mw2,
                                            mb2, minit);
    k_scatter<<<256, 256>>>(robj);
    k_bsort<<<256, 256>>>(rsub);
    k_p12<<<256, 256>>>(semb, w1);
    k_rel2<<<1024, 256>>>(b1, w2, b2);
    k_init<<<512, 256>>>(x);
    cudaEventRecord(evJ, s1);
    cudaStreamWaitEvent(0, evJ, 0);

    for (int t = 0; t < LL; t++) {
        k_stepG<<<512, 256>>>(t);
    }
    k_out<<<dim3(16, 32), 256>>>(out);
}

// round 15
// speedup vs baseline: 1.0332x; 1.0169x over previous
#include <cuda_runtime.h>

#define BB 64
#define SZ 2048
#define LL 16
#define AA 64
#define HH 256
#define RR 65536
#define XW (SZ + LL)

#define MW1_PITCH 196   // 192 + 4 pad; stride%8==4 -> conflict-free LDS.128 phases
#define MW1_SMEM_BYTES (256 * MW1_PITCH * 4)

// ---------------- scratch (static device globals; no allocs) ----------------
__device__ __align__(16) float    g_P1[SZ * HH];
__device__ __align__(16) float    g_P2[SZ * HH];
__device__ __align__(16) unsigned g_relB[RR * 32];        // relation rows, bf16x2 pairs, CSR order
__device__ __align__(16) unsigned g_metaB[LL * BB * 32];  // meta bf16x2 pairs [(t*64+b)*32 + kp]
__device__ __align__(16) float    g_stateAll[LL + 1][SZ * BB]; // [t][o][b]
__device__ int g_perm[RR];
__device__ int g_subjS[RR];
__device__ int g_objS[RR];
__device__ int g_counts[SZ];      // zero-initialized at load; re-zeroed by k_scatter
__device__ int g_rowptr[SZ + 1];
__device__ int g_offs[SZ];

// ---------------- mma helpers ----------------
__device__ __forceinline__ unsigned f2t(float f) {
    unsigned u;
    asm("cvt.rna.tf32.f32 %0, %1;" : "=r"(u) : "f"(f));
    return u;
}
__device__ __forceinline__ unsigned pk(float lo, float hi) {  // bf16x2 {hi,lo}
    unsigned r;
    asm("cvt.rn.bf16x2.f32 %0, %1, %2;" : "=r"(r) : "f"(hi), "f"(lo));
    return r;
}
__device__ __forceinline__ void mma8(float4& d, unsigned a0, unsigned a1, unsigned a2,
                                     unsigned a3, unsigned b0, unsigned b1) {
    asm volatile(
        "mma.sync.aligned.m16n8k8.row.col.f32.tf32.tf32.f32 "
        "{%0,%1,%2,%3},{%4,%5,%6,%7},{%8,%9},{%0,%1,%2,%3};"
        : "+f"(d.x), "+f"(d.y), "+f"(d.z), "+f"(d.w)
        : "r"(a0), "r"(a1), "r"(a2), "r"(a3), "r"(b0), "r"(b1));
}
__device__ __forceinline__ void mma16(float4& d, unsigned a0, unsigned a1, unsigned a2,
                                      unsigned a3, unsigned b0, unsigned b1) {
    asm volatile(
        "mma.sync.aligned.m16n8k16.row.col.f32.bf16.bf16.f32 "
        "{%0,%1,%2,%3},{%4,%5,%6,%7},{%8,%9},{%0,%1,%2,%3};"
        : "+f"(d.x), "+f"(d.y), "+f"(d.z), "+f"(d.w)
        : "r"(a0), "r"(a1), "r"(a2), "r"(a3), "r"(b0), "r"(b1));
}

__device__ __forceinline__ float sigf(float v) {
    return __fdividef(1.f, 1.f + __expf(-v));
}

// ---------------- CSR build (deterministic) ----------------
__global__ void k_hist(const int* __restrict__ robj) {
    int e = blockIdx.x * blockDim.x + threadIdx.x;
    if (e < RR) atomicAdd(&g_counts[robj[e]], 1);
}

__global__ void k_scan() {  // 1 block, 1024 threads: scan of 2048
    __shared__ int sA[SZ], sB[SZ];
    int tid = threadIdx.x;
    for (int i = tid; i < SZ; i += 1024) sA[i] = g_counts[i];
    __syncthreads();
    int* src = sA; int* dst = sB;
    for (int off = 1; off < SZ; off <<= 1) {
        for (int i = tid; i < SZ; i += 1024)
            dst[i] = src[i] + (i >= off ? src[i - off] : 0);
        __syncthreads();
        int* t = src; src = dst; dst = t;
    }
    for (int i = tid; i < SZ; i += 1024) {
        g_rowptr[i + 1] = src[i];
        g_offs[i] = (i == 0) ? 0 : src[i - 1];
    }
    if (tid == 0) g_rowptr[0] = 0;
}

__global__ void k_scatter(const int* __restrict__ robj) {
    int e = blockIdx.x * blockDim.x + threadIdx.x;
    if (e < RR) {
        int pos = atomicAdd(&g_offs[robj[e]], 1);
        g_perm[pos] = e;
    }
    // counts already consumed by k_scan; zero for the NEXT kernel_launch call
    // (graph replays run this identically; g_counts is zero-init at load).
    if (e < SZ) g_counts[e] = 0;
}

// rank-sort each bucket's edge ids ascending (determinism) — no serial rounds.
// Emit subj/obj in sorted order.
__global__ void k_bsort(const int* __restrict__ rsub) {
    __shared__ int buf[8][208];
    int wid = threadIdx.x >> 5, lane = threadIdx.x & 31;
    int o = blockIdx.x * 8 + wid;
    int s = g_rowptr[o], e = g_rowptr[o + 1], n = e - s;
    if (n > 0 && n <= 208) {
        for (int i = lane; i < n; i += 32) buf[wid][i] = g_perm[s + i];
        __syncwarp();
        for (int i = lane; i < n; i += 32) {
            int p = buf[wid][i];
            int rank = 0;
            for (int j = 0; j < n; j++) rank += (buf[wid][j] < p);
            g_perm[s + rank] = p;
            g_subjS[s + rank] = rsub[p];
            g_objS[s + rank] = o;
        }
    } else {
        for (int i = lane; i < n; i += 32) {
            int p = g_perm[s + i];
            g_subjS[s + i] = rsub[p];
            g_objS[s + i] = o;
        }
    }
}

// ---------------- P1/P2 = state_emb @ W1 halves ----------------
__global__ void k_p12(const float* __restrict__ emb, const float* __restrict__ w1) {
    __shared__ float es[8][64];
    int tid = threadIdx.x;
    int r0 = blockIdx.x * 8;
    for (int i = tid; i < 512; i += 256) es[i >> 6][i & 63] = emb[r0 * 64 + i];
    __syncthreads();
    float a1[8], a2[8];
#pragma unroll
    for (int r = 0; r < 8; r++) { a1[r] = 0.f; a2[r] = 0.f; }
    for (int k = 0; k < 64; k++) {
        float wa = w1[k * HH + tid];
        float wb = w1[(64 + k) * HH + tid];
#pragma unroll
        for (int r = 0; r < 8; r++) {
            a1[r] += es[r][k] * wa;
            a2[r] += es[r][k] * wb;
        }
    }
#pragma unroll
    for (int r = 0; r < 8; r++) {
        g_P1[(r0 + r) * HH + tid] = a1[r];
        g_P2[(r0 + r) * HH + tid] = a2[r];
    }
}

// ---------------- meta recurrence: one batch per block, mw1 resident in smem ------
// Forked at t=0 on its own stream; overlapped with the whole CSR/rel2 chain.
__global__ void __launch_bounds__(256) k_meta(
        const int* __restrict__ x, const float* __restrict__ aemb,
        const float* __restrict__ pemb, const float* __restrict__ qw,
        const float* __restrict__ qb, const float* __restrict__ mw1,
        const float* __restrict__ mb1, const float* __restrict__ mw2,
        const float* __restrict__ mb2, const float* __restrict__ minit) {
    extern __shared__ __align__(16) float sW[];   // [256][MW1_PITCH]
    __shared__ __align__(16) float sent[16][132];
    __shared__ __align__(16) float meta[64];
    __shared__ __align__(16) float query[128];
    __shared__ float attn[16];
    __shared__ __align__(16) float z[192];
    __shared__ __align__(16) float hid[256];
    int t = threadIdx.x;
    int b = blockIdx.x;

    for (int k = 0; k < 192; k++) sW[t * MW1_PITCH + k] = mw1[k * HH + t];

    for (int i = t; i < 16 * 128; i += 256) {
        int l = i >> 7, d = i & 127;
        int a = x[b * XW + SZ + l];
        sent[l][d] = (d < 64) ? aemb[a * 64 + d] : pemb[l * 64 + (d - 64)];
    }
    if (t < 64) meta[t] = minit[t];
    __syncthreads();

    for (int st = 0; st < 16; st++) {
        {
            int j = t >> 1, s = t & 1;
            float q = 0.f;
#pragma unroll
            for (int k = s * 32; k < s * 32 + 32; k++) q += meta[k] * qw[k * 128 + j];
            q += __shfl_xor_sync(0xffffffffu, q, 1);
            if (s == 0) query[j] = q + qb[j];
        }
        __syncthreads();
        {
            int l = t >> 4, s = t & 15;
            float sc = 0.f;
#pragma unroll
            for (int i = 0; i < 8; i++) {
                int d = s + 16 * i;
                sc += query[d] * sent[l][d];
            }
            sc += __shfl_xor_sync(0xffffffffu, sc, 1);
            sc += __shfl_xor_sync(0xffffffffu, sc, 2);
            sc += __shfl_xor_sync(0xffffffffu, sc, 4);
            sc += __shfl_xor_sync(0xffffffffu, sc, 8);
            if (s == 0) attn[l] = sc;
        }
        __syncthreads();
        if (t < 16) {
            float v = attn[t];
            float m = v;
#pragma unroll
            for (int o = 8; o; o >>= 1) m = fmaxf(m, __shfl_xor_sync(0xffffu, m, o));
            float e = __expf(v - m);
            float ssum = e;
#pragma unroll
            for (int o = 8; o; o >>= 1) ssum += __shfl_xor_sync(0xffffu, ssum, o);
            attn[t] = e / ssum;
        }
        __syncthreads();
        {
            int j = t >> 1, s = t & 1;
            float at = 0.f;
#pragma unroll
            for (int l = s * 8; l < s * 8 + 8; l++) at += attn[l] * sent[l][j];
            at += __shfl_xor_sync(0xffffffffu, at, 1);
            if (s == 0) {
                z[64 + j] = at;
                if (j < 64) z[j] = meta[j];
            }
        }
        __syncthreads();
        {
            const float4* wrow = (const float4*)&sW[t * MW1_PITCH];
            const float4* z4 = (const float4*)z;
            float a0 = 0.f, a1 = 0.f, a2 = 0.f, a3 = 0.f;
#pragma unroll
            for (int i = 0; i < 48; i += 4) {
                float4 w0 = wrow[i],     zv0 = z4[i];
                float4 w1v = wrow[i + 1], zv1 = z4[i + 1];
                float4 w2v = wrow[i + 2], zv2 = z4[i + 2];
                float4 w3v = wrow[i + 3], zv3 = z4[i + 3];
                a0 += w0.x * zv0.x + w0.y * zv0.y + w0.z * zv0.z + w0.w * zv0.w;
                a1 += w1v.x * zv1.x + w1v.y * zv1.y + w1v.z * zv1.z + w1v.w * zv1.w;
                a2 += w2v.x * zv2.x + w2v.y * zv2.y + w2v.z * zv2.z + w2v.w * zv2.w;
                a3 += w3v.x * zv3.x + w3v.y * zv3.y + w3v.z * zv3.z + w3v.w * zv3.w;
            }
            hid[t] = fmaxf((a0 + a1) + (a2 + a3) + mb1[t], 0.f);
        }
        __syncthreads();
        {
            int j = t >> 2, s = t & 3;
            float a0 = 0.f, a1 = 0.f;
#pragma unroll
            for (int i = 0; i < 64; i += 2) {
                a0 += hid[4 * i + s]       * mw2[(4 * i + s) * 64 + j];
                a1 += hid[4 * (i + 1) + s] * mw2[(4 * (i + 1) + s) * 64 + j];
            }
            float m = a0 + a1;
            m += __shfl_xor_sync(0xffffffffu, m, 1);
            m += __shfl_xor_sync(0xffffffffu, m, 2);
            if (s == 0) meta[j] = m + mb2[j];
        }
        __syncthreads();
        if (t < 32) g_metaB[(st * 64 + b) * 32 + t] = pk(meta[2 * t], meta[2 * t + 1]);
    }
}

// ---------------- relation rows via tf32 mma (CVT hoisted); output bf16 pairs ------
// block: 64 edges, N=64, K=256 in 4 chunks of 64. 256 threads = 8 warps (4m x 2n).
__global__ void k_rel2(const float* __restrict__ b1v, const float* __restrict__ w2,
                       const float* __restrict__ b2v) {
    __shared__ unsigned hs[64][68];   // tf32 bits
    __shared__ unsigned ws[64][68];   // tf32 bits
    __shared__ int ssub[64], sobj[64];
    int tid = threadIdx.x;
    int e0 = blockIdx.x * 64;
    if (tid < 64) { ssub[tid] = g_subjS[e0 + tid]; sobj[tid] = g_objS[e0 + tid]; }
    __syncthreads();
    int warp = tid >> 5, lane = tid & 31;
    int wm = warp & 3, wn = warp >> 2;
    int g = lane >> 2, tg = lane & 3;
    int r0 = wm * 16, n0 = wn * 32;
    float4 acc[4] = {};
    for (int kc = 0; kc < 4; kc++) {
        for (int i = tid; i < 64 * 16; i += 256) {
            int r = i >> 4, c = (i & 15) * 4;
            float4 p1 = *(const float4*)&g_P1[ssub[r] * HH + kc * 64 + c];
            float4 p2 = *(const float4*)&g_P2[sobj[r] * HH + kc * 64 + c];
            float4 bb = *(const float4*)&b1v[kc * 64 + c];
            uint4 h;
            h.x = f2t(fmaxf(p1.x + p2.x + bb.x, 0.f));
            h.y = f2t(fmaxf(p1.y + p2.y + bb.y, 0.f));
            h.z = f2t(fmaxf(p1.z + p2.z + bb.z, 0.f));
            h.w = f2t(fmaxf(p1.w + p2.w + bb.w, 0.f));
            *(uint4*)&hs[r][c] = h;
            float4 w = *(const float4*)&w2[(kc * 64 + r) * 64 + c];
            uint4 wv = {f2t(w.x), f2t(w.y), f2t(w.z), f2t(w.w)};
            *(uint4*)&ws[r][c] = wv;
        }
        __syncthreads();
#pragma unroll
        for (int ks = 0; ks < 8; ks++) {
            int kk = ks * 8;
            unsigned a0 = hs[r0 + g][kk + tg];
            unsigned a1 = hs[r0 + g + 8][kk + tg];
            unsigned a2 = hs[r0 + g][kk + tg + 4];
            unsigned a3 = hs[r0 + g + 8][kk + tg + 4];
#pragma unroll
            for (int nf = 0; nf < 4; nf++) {
                int n = n0 + nf * 8 + g;
                mma8(acc[nf], a0, a1, a2, a3, ws[kk + tg][n], ws[kk + tg + 4][n]);
            }
        }
        __syncthreads();
    }
#pragma unroll
    for (int nf = 0; nf < 4; nf++) {
        int col = n0 + nf * 8 + 2 * tg;
        float bx = b2v[col], by = b2v[col + 1];
        int row = e0 + r0 + g;
        int pi = (n0 + nf * 8) / 2 + tg;   // pair index = col/2
        g_relB[row * 32 + pi] = pk(acc[nf].x + bx, acc[nf].y + by);
        g_relB[(row + 8) * 32 + pi] = pk(acc[nf].z + bx, acc[nf].w + by);
    }
}

// ---------------- init: state[0] from x, zero state[1] ----------------
__global__ void k_init(const int* __restrict__ x) {
    int i = blockIdx.x * blockDim.x + threadIdx.x;  // 131072
    int b = i >> 11, o = i & 2047;
    g_stateAll[0][o * 64 + b] = (float)x[b * XW + o];
    g_stateAll[1][i] = 0.f;
}

// ---------------- fused step, bf16: 512 blocks x two 64-edge tiles (one wave) ------
// bf16 m16n8k16 dots + prefetched state gather + sigmoid + run-segmented atomics.
// Also zeros state[t+2] (the NEXT step's accumulation target).
__global__ void __launch_bounds__(256) k_stepG(int t) {
    __shared__ __align__(16) float prod[64 * 68];
    __shared__ __align__(16) unsigned relS[2][64 * 36];
    __shared__ __align__(16) unsigned metaS[64 * 36];
    __shared__ int ssubj[2][64];
    __shared__ int sobj[2][64];
    const float* __restrict__ stIn = g_stateAll[t];
    float* __restrict__ stOut = g_stateAll[t + 1];
    int tid = threadIdx.x;
    int e0 = blockIdx.x * 128;

    const unsigned* mt = &g_metaB[t * 2048];
    for (int i = tid; i < 512; i += 256) {
        int r = i >> 3, c4 = (i & 7) * 4;
        *(uint4*)&metaS[r * 36 + c4] = *(const uint4*)&mt[r * 32 + c4];
        *(uint4*)&relS[0][r * 36 + c4] = *(const uint4*)&g_relB[(e0 + r) * 32 + c4];
        *(uint4*)&relS[1][r * 36 + c4] = *(const uint4*)&g_relB[(e0 + 64 + r) * 32 + c4];
    }
    if (tid < 128) {
        int h = tid >> 6, r = tid & 63;
        ssubj[h][r] = g_subjS[e0 + h * 64 + r];
        sobj[h][r] = g_objS[e0 + h * 64 + r];
    }
    if (t + 2 <= LL && tid < 64) {
        ((float4*)&g_stateAll[t + 2][blockIdx.x * 256])[tid] =
            make_float4(0.f, 0.f, 0.f, 0.f);
    }
    __syncthreads();

    int warp = tid >> 5, lane = tid & 31;
    int wm = warp & 3, wn = warp >> 2;
    int g = lane >> 2, tg = lane & 3;
    int r0 = wm * 16, n0 = wn * 32;
    int rA = r0 + g, rB = rA + 8;
    int q = tid >> 6, col = tid & 63;

    // prefetch state gathers for tile 0 (hidden behind the MMA stream)
    float2 pre[8];
    {
        int sjA = ssubj[0][rA], sjB = ssubj[0][rB];
#pragma unroll
        for (int nf = 0; nf < 4; nf++) {
            int c = n0 + nf * 8 + 2 * tg;
            pre[nf]     = __ldcg((const float2*)&stIn[sjA * 64 + c]);
            pre[4 + nf] = __ldcg((const float2*)&stIn[sjB * 64 + c]);
        }
    }

#pragma unroll
    for (int h = 0; h < 2; h++) {
        float4 accf[4] = {};
#pragma unroll
        for (int ks = 0; ks < 4; ks++) {
            int kp = ks * 8;
            unsigned a0 = relS[h][rA * 36 + kp + tg];
            unsigned a1 = relS[h][rB * 36 + kp + tg];
            unsigned a2 = relS[h][rA * 36 + kp + tg + 4];
            unsigned a3 = relS[h][rB * 36 + kp + tg + 4];
#pragma unroll
            for (int nf = 0; nf < 4; nf++) {
                int n = n0 + nf * 8 + g;
                mma16(accf[nf], a0, a1, a2, a3,
                      metaS[n * 36 + kp + tg], metaS[n * 36 + kp + tg + 4]);
            }
        }

        // epilogue: prod[e][b] = state[subj[e]][b] * sigmoid(D[e][b])
#pragma unroll
        for (int nf = 0; nf < 4; nf++) {
            int c = n0 + nf * 8 + 2 * tg;
            float2 svA = pre[nf];
            float2 svB = pre[4 + nf];
            float2 pA = {svA.x * sigf(accf[nf].x), svA.y * sigf(accf[nf].y)};
            float2 pB = {svB.x * sigf(accf[nf].z), svB.y * sigf(accf[nf].w)};
            *(float2*)&prod[rA * 68 + c] = pA;
            *(float2*)&prod[rB * 68 + c] = pB;
        }
        if (h == 0) {   // prefetch tile 1's gathers before the barrier
            int sjA = ssubj[1][rA], sjB = ssubj[1][rB];
#pragma unroll
            for (int nf = 0; nf < 4; nf++) {
                int c = n0 + nf * 8 + 2 * tg;
                pre[nf]     = __ldcg((const float2*)&stIn[sjA * 64 + c]);
                pre[4 + nf] = __ldcg((const float2*)&stIn[sjB * 64 + c]);
            }
        }
        __syncthreads();

        // run-segmented reduction: thread (q,col) sums rows [16q,16q+16) by bucket,
        // emitting one global atomicAdd per run (buckets may span blocks).
        {
            float s = 0.f;
            int cur = sobj[h][q * 16];
#pragma unroll
            for (int r = q * 16; r < q * 16 + 16; r++) {
                int o = sobj[h][r];
                if (o != cur) {
                    atomicAdd(&stOut[cur * 64 + col], s);
                    s = 0.f; cur = o;
                }
                s += prod[r * 68 + col];
            }
            atomicAdd(&stOut[cur * 64 + col], s);
        }
        if (h == 0) __syncthreads();  // all reduce reads done before prod rewrite
    }
}

// ---------------- final transpose: out[b][t][o] = stateAll[t+1][o][b] -------------
__global__ void k_out(float* __restrict__ out) {
    __shared__ float tile[64][65];
    int t = blockIdx.x, o0 = blockIdx.y * 64;
    const float* st = g_stateAll[t + 1];
    for (int i = threadIdx.x; i < 64 * 64; i += 256) {
        int r = i >> 6, b = i & 63;
        tile[b][r] = st[(o0 + r) * 64 + b];
    }
    __syncthreads();
    for (int i = threadIdx.x; i < 64 * 64; i += 256) {
        int b = i >> 6, c = i & 63;
        out[(size_t)b * (LL * SZ) + t * SZ + o0 + c] = tile[b][c];
    }
}

extern "C" void kernel_launch(void* const* d_in, const int* in_sizes, int n_in,
                              void* d_out, int out_size) {
    const int*   x     = (const int*)d_in[0];
    const int*   rsub  = (const int*)d_in[1];
    const int*   robj  = (const int*)d_in[2];
    const float* aemb  = (const float*)d_in[3];
    const float* pemb  = (const float*)d_in[4];
    const float* semb  = (const float*)d_in[5];
    const float* w1    = (const float*)d_in[6];
    const float* b1    = (const float*)d_in[7];
    const float* w2    = (const float*)d_in[8];
    const float* b2    = (const float*)d_in[9];
    const float* qw    = (const float*)d_in[10];
    const float* qb    = (const float*)d_in[11];
    const float* mw1   = (const float*)d_in[12];
    const float* mb1   = (const float*)d_in[13];
    const float* mw2   = (const float*)d_in[14];
    const float* mb2   = (const float*)d_in[15];
    const float* minit = (const float*)d_in[16];
    float* out = (float*)d_out;

    // One-time resources: created on the FIRST (uncaptured) correctness call,
    // reused by the capture call. No device-memory allocation involved.
    static cudaStream_t s1 = nullptr, s2 = nullptr;
    static cudaEvent_t evF = nullptr, evJ1 = nullptr, evP = nullptr, evJ2 = nullptr;
    if (s1 == nullptr) {
        cudaStreamCreateWithFlags(&s1, cudaStreamNonBlocking);
        cudaStreamCreateWithFlags(&s2, cudaStreamNonBlocking);
        cudaEventCreateWithFlags(&evF, cudaEventDisableTiming);
        cudaEventCreateWithFlags(&evJ1, cudaEventDisableTiming);
        cudaEventCreateWithFlags(&evP, cudaEventDisableTiming);
        cudaEventCreateWithFlags(&evJ2, cudaEventDisableTiming);
        cudaFuncSetAttribute(k_meta, cudaFuncAttributeMaxDynamicSharedMemorySize,
                             MW1_SMEM_BYTES);
    }

    // Fork AT T=0: s1 runs meta (depends only on inputs); s2 runs p12 then init.
    // Main stream runs the CSR chain. g_counts is zero here (static init on the
    // first call; re-zeroed by the previous call's k_scatter afterwards).
    cudaEventRecord(evF, 0);
    cudaStreamWaitEvent(s1, evF, 0);
    cudaStreamWaitEvent(s2, evF, 0);
    k_meta<<<64, 256, MW1_SMEM_BYTES, s1>>>(x, aemb, pemb, qw, qb, mw1, mb1, mw2,
                                            mb2, minit);
    cudaEventRecord(evJ1, s1);
    k_p12<<<256, 256, 0, s2>>>(semb, w1);
    cudaEventRecord(evP, s2);
    k_init<<<512, 256, 0, s2>>>(x);
    cudaEventRecord(evJ2, s2);

    k_hist<<<256, 256>>>(robj);
    k_scan<<<1, 1024>>>();
    k_scatter<<<256, 256>>>(robj);
    k_bsort<<<256, 256>>>(rsub);
    cudaStreamWaitEvent(0, evP, 0);   // rel2 needs P1/P2
    k_rel2<<<1024, 256>>>(b1, w2, b2);
    cudaStreamWaitEvent(0, evJ1, 0);  // steps need metaB
    cudaStreamWaitEvent(0, evJ2, 0);  // steps need state init

    for (int t = 0; t < LL; t++) {
        k_stepG<<<512, 256>>>(t);
    }
    k_out<<<dim3(16, 32), 256>>>(out);
}